// round 3
// baseline (speedup 1.0000x reference)
#include <cuda_runtime.h>

#define N_ATOMS 50000
#define N_PAIRS 800000
#define N_EMB   128
#define N_DIST  100
#define N_HID   128

typedef unsigned long long ull;

// Scratch: atom hidden features (atom_features @ W_cf + b_cf), 25.6 MB.
__device__ float g_afh[(size_t)N_ATOMS * N_HID];

// ---------- packed f32x2 helpers (full-rate fp32 on sm_103a) ----------
static __device__ __forceinline__ void ffma2(ull &acc, ull a, ull b) {
    asm("fma.rn.f32x2 %0, %1, %2, %0;" : "+l"(acc) : "l"(a), "l"(b));
}
static __device__ __forceinline__ ull mul2(ull a, ull b) {
    ull r; asm("mul.rn.f32x2 %0, %1, %2;" : "=l"(r) : "l"(a), "l"(b)); return r;
}
static __device__ __forceinline__ ull pack2(float lo, float hi) {
    ull r; asm("mov.b64 %0, {%1, %2};" : "=l"(r) : "f"(lo), "f"(hi)); return r;
}
static __device__ __forceinline__ ull dup2(float v) {
    ull r; asm("mov.b64 %0, {%1, %1};" : "=l"(r) : "f"(v)); return r;
}
static __device__ __forceinline__ void unpack2(ull p, float &lo, float &hi) {
    asm("mov.b64 {%0, %1}, %2;" : "=f"(lo), "=f"(hi) : "l"(p));
}

// ~1e-6-accurate tanh from 2 MUFU ops.
static __device__ __forceinline__ float fast_tanh(float x) {
    float e = __expf(2.0f * x);
    return 1.0f - __fdividef(2.0f, e + 1.0f);
}

// =====================================================================
// 4-row x 8-col micro-kernel, 4 k-steps per call.
// A loaded as float4 (row-major, k-contiguous), B as 2x LDS.128 per k.
// 12 LDS per 64 FFMA2.
// =====================================================================
template<int SA>
static __device__ __forceinline__ void gemm_step4x(
    const float* __restrict__ Arow,   // A + r0*SA
    const float* __restrict__ Bcol,   // Bs + c0
    int k4, ull acc[16])
{
    float4 a[4];
#pragma unroll
    for (int i = 0; i < 4; i++)
        a[i] = *(const float4*)(Arow + i * SA + k4);
#pragma unroll
    for (int kk = 0; kk < 4; kk++) {
        const float* Bk = Bcol + (k4 + kk) * 128;
        ulonglong2 b01 = *(const ulonglong2*)(Bk);
        ulonglong2 b23 = *(const ulonglong2*)(Bk + 4);
#pragma unroll
        for (int i = 0; i < 4; i++) {
            float av = (kk == 0) ? a[i].x : (kk == 1) ? a[i].y
                     : (kk == 2) ? a[i].z : a[i].w;
            ull a2 = dup2(av);
            ffma2(acc[i * 4 + 0], a2, b01.x);
            ffma2(acc[i * 4 + 1], a2, b01.y);
            ffma2(acc[i * 4 + 2], a2, b23.x);
            ffma2(acc[i * 4 + 3], a2, b23.y);
        }
    }
}

// =====================================================================
// Kernel 1 (atoms): unchanged structure from R2 (256 thr, 8x8 tile).
// Only ~3% of runtime; kept low-risk.
// =====================================================================
template<int SA>
static __device__ __forceinline__ void gemm_step8(
    const float* __restrict__ Arow,
    const float* __restrict__ Bk,
    int k, ull acc[32])
{
    ull a2[8];
#pragma unroll
    for (int i = 0; i < 8; i++) a2[i] = dup2(Arow[i * SA + k]);
    ulonglong2 b01 = *(const ulonglong2*)(Bk);
    ulonglong2 b23 = *(const ulonglong2*)(Bk + 4);
#pragma unroll
    for (int i = 0; i < 8; i++) {
        ffma2(acc[i * 4 + 0], a2[i], b01.x);
        ffma2(acc[i * 4 + 1], a2[i], b01.y);
        ffma2(acc[i * 4 + 2], a2[i], b23.x);
        ffma2(acc[i * 4 + 3], a2[i], b23.y);
    }
}

__global__ void __launch_bounds__(256, 1) atoms_kernel(
    const float* __restrict__ atom_features,
    const float* __restrict__ W_cf,
    const float* __restrict__ W_fc,
    const float* __restrict__ b_cf,
    const float* __restrict__ b_df,
    float* __restrict__ out)
{
    extern __shared__ float smem[];
    float* bcf_s = smem;
    float* bdf_s = smem + 128;
    float* Af    = smem + 256;      // 128 x 132
    float* Ms    = Af + 128 * 132;  // 128 x 132
    float* Bs    = Ms + 128 * 132;  // 128 x 128

    const int tid = threadIdx.x;
    const int tx = tid & 15, ty = tid >> 4;
    const int c0 = tx * 8, r0 = ty * 8;
    const int base = blockIdx.x * 128;
    const int rows = min(128, N_ATOMS - base);

    if (tid < 128) { bcf_s[tid] = b_cf[tid]; bdf_s[tid] = b_df[tid]; }
    for (int idx = tid; idx < 128 * 32; idx += 256) {
        int rr = idx >> 5, q = idx & 31;
        float4 v = make_float4(0.f, 0.f, 0.f, 0.f);
        if (rr < rows) v = ((const float4*)atom_features)[(size_t)(base + rr) * 32 + q];
        ((float4*)Af)[rr * 33 + q] = v;
        ((float4*)Bs)[idx] = ((const float4*)W_cf)[idx];
    }
    __syncthreads();

    ull acc[32];
    {
        ull b[4];
#pragma unroll
        for (int q = 0; q < 4; q++) b[q] = pack2(bcf_s[c0 + 2*q], bcf_s[c0 + 2*q + 1]);
#pragma unroll
        for (int i = 0; i < 8; i++)
#pragma unroll
            for (int q = 0; q < 4; q++) acc[i * 4 + q] = b[q];
    }
    {
        const float* Arow = Af + r0 * 132;
        const float* Bc   = Bs + c0;
#pragma unroll 2
        for (int k = 0; k < 128; k++) gemm_step8<132>(Arow, Bc + k * 128, k, acc);
    }

#pragma unroll
    for (int i = 0; i < 8; i++) {
        if (base + r0 + i < N_ATOMS) {
            ull* arow = (ull*)(g_afh + (size_t)(base + r0 + i) * N_HID + c0);
#pragma unroll
            for (int q = 0; q < 4; q++) arow[q] = acc[i * 4 + q];
        }
    }
    __syncthreads();
#pragma unroll
    for (int i = 0; i < 8; i++) {
        ulonglong2 m01, m23;
        m01.x = mul2(acc[i*4+0], pack2(bdf_s[c0+0], bdf_s[c0+1]));
        m01.y = mul2(acc[i*4+1], pack2(bdf_s[c0+2], bdf_s[c0+3]));
        m23.x = mul2(acc[i*4+2], pack2(bdf_s[c0+4], bdf_s[c0+5]));
        m23.y = mul2(acc[i*4+3], pack2(bdf_s[c0+6], bdf_s[c0+7]));
        *(ulonglong2*)(Ms + (r0 + i) * 132 + c0)     = m01;
        *(ulonglong2*)(Ms + (r0 + i) * 132 + c0 + 4) = m23;
    }
    for (int idx = tid; idx < 128 * 32; idx += 256)
        ((float4*)Bs)[idx] = ((const float4*)W_fc)[idx];
    __syncthreads();

#pragma unroll
    for (int i = 0; i < 32; i++) acc[i] = 0ULL;
    {
        const float* Arow = Ms + r0 * 132;
        const float* Bc   = Bs + c0;
#pragma unroll 2
        for (int k = 0; k < 128; k++) gemm_step8<132>(Arow, Bc + k * 128, k, acc);
    }

#pragma unroll
    for (int i = 0; i < 8; i++) {
        if (base + r0 + i < N_ATOMS) {
            float* orow = out + (size_t)(base + r0 + i) * N_EMB + c0;
            const float* af = Af + (r0 + i) * 132 + c0;
#pragma unroll
            for (int q = 0; q < 4; q++) {
                float lo, hi; unpack2(acc[i * 4 + q], lo, hi);
                orow[2 * q]     = af[2 * q]     - fast_tanh(lo);
                orow[2 * q + 1] = af[2 * q + 1] - fast_tanh(hi);
            }
        }
    }
}

// =====================================================================
// Kernel 2 (pairs): 512 threads, 4x8 per-thread tile over 128x128,
// float4 A loads, same smem as R2 (1 CTA/SM but 16 warps).
// dist lives in U at stride 132 (cols 0..99); m overwrites it in place.
// =====================================================================
__global__ void __launch_bounds__(512, 1) pairs_kernel(
    const float* __restrict__ distance,
    const int*   __restrict__ dmi,
    const int*   __restrict__ dmj,
    const float* __restrict__ W_df,
    const float* __restrict__ W_fc,
    const float* __restrict__ b_df,
    float* __restrict__ out)
{
    extern __shared__ float smem[];
    int*   i_s   = (int*)smem;            // 128
    int*   j_s   = ((int*)smem) + 128;    // 128
    float* bdf_s = smem + 256;            // 128
    float* U     = smem + 384;            // 128 x 132 (dist cols 0..99, then m)
    float* Bs    = U + 128 * 132;         // 128 x 128

    const int tid = threadIdx.x;
    const int tx = tid & 15, ty = tid >> 4;   // ty: 0..31
    const int c0 = tx * 8, r0 = ty * 4;
    const int pbase = blockIdx.x * 128;

    if (tid < 128) {
        i_s[tid]   = dmi[pbase + tid];
        j_s[tid]   = dmj[pbase + tid];
        bdf_s[tid] = b_df[tid];
    }
    // distance tile: 128 rows x 25 float4 into stride-132 rows (33 f4)
    for (int idx = tid; idx < 128 * 25; idx += 512) {
        int rr = idx / 25, q = idx - rr * 25;
        ((float4*)U)[rr * 33 + q] =
            ((const float4*)distance)[(size_t)pbase * 25 + idx];
    }
    for (int idx = tid; idx < 100 * 32; idx += 512)
        ((float4*)Bs)[idx] = ((const float4*)W_df)[idx];
    __syncthreads();

    ull acc[16];
    {
        ull b[4];
#pragma unroll
        for (int q = 0; q < 4; q++) b[q] = pack2(bdf_s[c0 + 2*q], bdf_s[c0 + 2*q + 1]);
#pragma unroll
        for (int i = 0; i < 4; i++)
#pragma unroll
            for (int q = 0; q < 4; q++) acc[i * 4 + q] = b[q];
    }
    {   // GEMM1: dh = dist @ W_df + b_df   (K = 100 = 25 x 4)
        const float* Arow = U + r0 * 132;
        const float* Bc   = Bs + c0;
#pragma unroll 2
        for (int k4 = 0; k4 < N_DIST; k4 += 4) gemm_step4x<132>(Arow, Bc, k4, acc);
    }

    // m = dh * afh[j]   (gather, L2-resident table; register-only)
#pragma unroll
    for (int i = 0; i < 4; i++) {
        const int j = j_s[r0 + i];
        const ulonglong2* ar = (const ulonglong2*)(g_afh + (size_t)j * N_HID + c0);
        ulonglong2 g01 = ar[0], g23 = ar[1];
        acc[i*4+0] = mul2(acc[i*4+0], g01.x);
        acc[i*4+1] = mul2(acc[i*4+1], g01.y);
        acc[i*4+2] = mul2(acc[i*4+2], g23.x);
        acc[i*4+3] = mul2(acc[i*4+3], g23.y);
    }
    __syncthreads();   // all GEMM1 reads of U/Bs complete

    // store m row-major into U (stride 132); overwrite Bs with W_fc
#pragma unroll
    for (int i = 0; i < 4; i++) {
        ulonglong2 m01, m23;
        m01.x = acc[i*4+0]; m01.y = acc[i*4+1];
        m23.x = acc[i*4+2]; m23.y = acc[i*4+3];
        *(ulonglong2*)(U + (r0 + i) * 132 + c0)     = m01;
        *(ulonglong2*)(U + (r0 + i) * 132 + c0 + 4) = m23;
    }
    for (int idx = tid; idx < 128 * 32; idx += 512)
        ((float4*)Bs)[idx] = ((const float4*)W_fc)[idx];
    __syncthreads();

    // GEMM2: pre = m @ W_fc   (K = 128 = 32 x 4)
#pragma unroll
    for (int i = 0; i < 16; i++) acc[i] = 0ULL;
    {
        const float* Arow = U + r0 * 132;
        const float* Bc   = Bs + c0;
#pragma unroll 2
        for (int k4 = 0; k4 < N_HID; k4 += 4) gemm_step4x<132>(Arow, Bc, k4, acc);
    }
    __syncthreads();   // all GEMM2 reads of U done

    // msg = tanh(pre) -> U
#pragma unroll
    for (int i = 0; i < 4; i++) {
        float* mrow = U + (r0 + i) * 132 + c0;
#pragma unroll
        for (int q = 0; q < 4; q++) {
            float lo, hi; unpack2(acc[i * 4 + q], lo, hi);
            mrow[2 * q]     = fast_tanh(lo);
            mrow[2 * q + 1] = fast_tanh(hi);
        }
    }
    __syncthreads();

    // Segmented reduction over sorted i: 512 threads = 128 cols x 4 quarters.
    {
        const int c  = tid & 127;
        const int h0 = (tid >> 7) << 5;   // 0, 32, 64, 96
        int   cur = i_s[h0];
        float sum = 0.0f;
        for (int rr = h0; rr < h0 + 32; rr++) {
            int ii = i_s[rr];
            if (ii != cur) {
                atomicAdd(out + (size_t)cur * N_EMB + c, sum);
                cur = ii; sum = 0.0f;
            }
            sum += U[rr * 132 + c];
        }
        atomicAdd(out + (size_t)cur * N_EMB + c, sum);
    }
}

// =====================================================================
extern "C" void kernel_launch(void* const* d_in, const int* in_sizes, int n_in,
                              void* d_out, int out_size)
{
    const float* atom_features = (const float*)d_in[0];
    const float* distance      = (const float*)d_in[1];
    const int*   dmi           = (const int*)d_in[3];
    const int*   dmj           = (const int*)d_in[4];
    const float* W_cf          = (const float*)d_in[5];
    const float* W_df          = (const float*)d_in[6];
    const float* W_fc          = (const float*)d_in[7];
    const float* b_cf          = (const float*)d_in[8];
    const float* b_df          = (const float*)d_in[9];
    float*       out           = (float*)d_out;

    const int smemA = (256 + 128*132 + 128*132 + 128*128) * 4;   // 201728 B
    const int smemP = (384 + 128*132 + 128*128) * 4;             // 134656 B

    cudaFuncSetAttribute(atoms_kernel, cudaFuncAttributeMaxDynamicSharedMemorySize, smemA);
    cudaFuncSetAttribute(pairs_kernel, cudaFuncAttributeMaxDynamicSharedMemorySize, smemP);

    atoms_kernel<<<(N_ATOMS + 127) / 128, 256, smemA>>>(
        atom_features, W_cf, W_fc, b_cf, b_df, out);
    pairs_kernel<<<N_PAIRS / 128, 512, smemP>>>(
        distance, dmi, dmj, W_df, W_fc, b_df, out);
}

// round 4
// speedup vs baseline: 1.4447x; 1.4447x over previous
#include <cuda_runtime.h>

#define N_ATOMS 50000
#define N_PAIRS 800000
#define N_EMB   128
#define N_DIST  100
#define N_HID   128

typedef unsigned long long ull;

// Scratch: atom hidden features (atom_features @ W_cf + b_cf), 25.6 MB.
__device__ float g_afh[(size_t)N_ATOMS * N_HID];

// ---------- packed f32x2 helpers (full-rate fp32 on sm_103a) ----------
static __device__ __forceinline__ void ffma2(ull &acc, ull a, ull b) {
    asm("fma.rn.f32x2 %0, %1, %2, %0;" : "+l"(acc) : "l"(a), "l"(b));
}
static __device__ __forceinline__ ull mul2(ull a, ull b) {
    ull r; asm("mul.rn.f32x2 %0, %1, %2;" : "=l"(r) : "l"(a), "l"(b)); return r;
}
static __device__ __forceinline__ ull pack2(float lo, float hi) {
    ull r; asm("mov.b64 %0, {%1, %2};" : "=l"(r) : "f"(lo), "f"(hi)); return r;
}
static __device__ __forceinline__ ull dup2(float v) {
    ull r; asm("mov.b64 %0, {%1, %1};" : "=l"(r) : "f"(v)); return r;
}
static __device__ __forceinline__ void unpack2(ull p, float &lo, float &hi) {
    asm("mov.b64 {%0, %1}, %2;" : "=f"(lo), "=f"(hi) : "l"(p));
}

// ~1e-6-accurate tanh from 2 MUFU ops.
static __device__ __forceinline__ float fast_tanh(float x) {
    float e = __expf(2.0f * x);
    return 1.0f - __fdividef(2.0f, e + 1.0f);
}

// =====================================================================
// 8-row x 4-col micro-kernel, one 4k block per call.
// A: 8 float4 broadcast loads (all lanes same addr -> 1 wavefront each).
// B: 4 LDS.128 (one row of 4 cols per k), 512B/warp -> 4 wavefronts.
// 12 LDS issues per 64 FFMA2.
// =====================================================================
template<int SA>
static __device__ __forceinline__ void gemm_block8x4(
    const float* __restrict__ Arow,   // A + r0*SA
    const float* __restrict__ Bcol,   // Bs + c0
    int k4, ull acc[16])
{
    float4 a[8];
#pragma unroll
    for (int i = 0; i < 8; i++)
        a[i] = *(const float4*)(Arow + i * SA + k4);
    ulonglong2 b[4];
#pragma unroll
    for (int kk = 0; kk < 4; kk++)
        b[kk] = *(const ulonglong2*)(Bcol + (k4 + kk) * 128);
#pragma unroll
    for (int kk = 0; kk < 4; kk++) {
#pragma unroll
        for (int i = 0; i < 8; i++) {
            float av = (kk == 0) ? a[i].x : (kk == 1) ? a[i].y
                     : (kk == 2) ? a[i].z : a[i].w;
            ull a2 = dup2(av);
            ffma2(acc[2 * i],     a2, b[kk].x);
            ffma2(acc[2 * i + 1], a2, b[kk].y);
        }
    }
}

// =====================================================================
// Kernel 1 (atoms): R2 structure (256 thr, 8x8). ~3% of runtime.
// =====================================================================
template<int SA>
static __device__ __forceinline__ void gemm_step8(
    const float* __restrict__ Arow,
    const float* __restrict__ Bk,
    int k, ull acc[32])
{
    ull a2[8];
#pragma unroll
    for (int i = 0; i < 8; i++) a2[i] = dup2(Arow[i * SA + k]);
    ulonglong2 b01 = *(const ulonglong2*)(Bk);
    ulonglong2 b23 = *(const ulonglong2*)(Bk + 4);
#pragma unroll
    for (int i = 0; i < 8; i++) {
        ffma2(acc[i * 4 + 0], a2[i], b01.x);
        ffma2(acc[i * 4 + 1], a2[i], b01.y);
        ffma2(acc[i * 4 + 2], a2[i], b23.x);
        ffma2(acc[i * 4 + 3], a2[i], b23.y);
    }
}

__global__ void __launch_bounds__(256, 1) atoms_kernel(
    const float* __restrict__ atom_features,
    const float* __restrict__ W_cf,
    const float* __restrict__ W_fc,
    const float* __restrict__ b_cf,
    const float* __restrict__ b_df,
    float* __restrict__ out)
{
    extern __shared__ float smem[];
    float* bcf_s = smem;
    float* bdf_s = smem + 128;
    float* Af    = smem + 256;      // 128 x 132
    float* Ms    = Af + 128 * 132;  // 128 x 132
    float* Bs    = Ms + 128 * 132;  // 128 x 128

    const int tid = threadIdx.x;
    const int tx = tid & 15, ty = tid >> 4;
    const int c0 = tx * 8, r0 = ty * 8;
    const int base = blockIdx.x * 128;
    const int rows = min(128, N_ATOMS - base);

    if (tid < 128) { bcf_s[tid] = b_cf[tid]; bdf_s[tid] = b_df[tid]; }
    for (int idx = tid; idx < 128 * 32; idx += 256) {
        int rr = idx >> 5, q = idx & 31;
        float4 v = make_float4(0.f, 0.f, 0.f, 0.f);
        if (rr < rows) v = ((const float4*)atom_features)[(size_t)(base + rr) * 32 + q];
        ((float4*)Af)[rr * 33 + q] = v;
        ((float4*)Bs)[idx] = ((const float4*)W_cf)[idx];
    }
    __syncthreads();

    ull acc[32];
    {
        ull b[4];
#pragma unroll
        for (int q = 0; q < 4; q++) b[q] = pack2(bcf_s[c0 + 2*q], bcf_s[c0 + 2*q + 1]);
#pragma unroll
        for (int i = 0; i < 8; i++)
#pragma unroll
            for (int q = 0; q < 4; q++) acc[i * 4 + q] = b[q];
    }
    {
        const float* Arow = Af + r0 * 132;
        const float* Bc   = Bs + c0;
#pragma unroll 2
        for (int k = 0; k < 128; k++) gemm_step8<132>(Arow, Bc + k * 128, k, acc);
    }

#pragma unroll
    for (int i = 0; i < 8; i++) {
        if (base + r0 + i < N_ATOMS) {
            ull* arow = (ull*)(g_afh + (size_t)(base + r0 + i) * N_HID + c0);
#pragma unroll
            for (int q = 0; q < 4; q++) arow[q] = acc[i * 4 + q];
        }
    }
    __syncthreads();
#pragma unroll
    for (int i = 0; i < 8; i++) {
        ulonglong2 m01, m23;
        m01.x = mul2(acc[i*4+0], pack2(bdf_s[c0+0], bdf_s[c0+1]));
        m01.y = mul2(acc[i*4+1], pack2(bdf_s[c0+2], bdf_s[c0+3]));
        m23.x = mul2(acc[i*4+2], pack2(bdf_s[c0+4], bdf_s[c0+5]));
        m23.y = mul2(acc[i*4+3], pack2(bdf_s[c0+6], bdf_s[c0+7]));
        *(ulonglong2*)(Ms + (r0 + i) * 132 + c0)     = m01;
        *(ulonglong2*)(Ms + (r0 + i) * 132 + c0 + 4) = m23;
    }
    for (int idx = tid; idx < 128 * 32; idx += 256)
        ((float4*)Bs)[idx] = ((const float4*)W_fc)[idx];
    __syncthreads();

#pragma unroll
    for (int i = 0; i < 32; i++) acc[i] = 0ULL;
    {
        const float* Arow = Ms + r0 * 132;
        const float* Bc   = Bs + c0;
#pragma unroll 2
        for (int k = 0; k < 128; k++) gemm_step8<132>(Arow, Bc + k * 128, k, acc);
    }

#pragma unroll
    for (int i = 0; i < 8; i++) {
        if (base + r0 + i < N_ATOMS) {
            float* orow = out + (size_t)(base + r0 + i) * N_EMB + c0;
            const float* af = Af + (r0 + i) * 132 + c0;
#pragma unroll
            for (int q = 0; q < 4; q++) {
                float lo, hi; unpack2(acc[i * 4 + q], lo, hi);
                orow[2 * q]     = af[2 * q]     - fast_tanh(lo);
                orow[2 * q + 1] = af[2 * q + 1] - fast_tanh(hi);
            }
        }
    }
}

// =====================================================================
// Kernel 2 (pairs): 512 threads, 8x4 per-thread tile over 128x128.
//   tx = tid&31 -> c0 = tx*4 (32 col groups)
//   ty = tid>>5 -> r0 = ty*8 (16 row groups); warp = one ty -> A broadcast
// =====================================================================
__global__ void __launch_bounds__(512, 1) pairs_kernel(
    const float* __restrict__ distance,
    const int*   __restrict__ dmi,
    const int*   __restrict__ dmj,
    const float* __restrict__ W_df,
    const float* __restrict__ W_fc,
    const float* __restrict__ b_df,
    float* __restrict__ out)
{
    extern __shared__ float smem[];
    int*   i_s   = (int*)smem;            // 128
    int*   j_s   = ((int*)smem) + 128;    // 128
    float* bdf_s = smem + 256;            // 128
    float* U     = smem + 384;            // 128 x 132 (dist cols 0..99 -> m)
    float* Bs    = U + 128 * 132;         // 128 x 128

    const int tid = threadIdx.x;
    const int tx = tid & 31, ty = tid >> 5;
    const int c0 = tx * 4, r0 = ty * 8;
    const int pbase = blockIdx.x * 128;

    if (tid < 128) {
        i_s[tid]   = dmi[pbase + tid];
        j_s[tid]   = dmj[pbase + tid];
        bdf_s[tid] = b_df[tid];
    }
    // distance tile: 128 rows x 25 float4 into stride-132 rows (33 f4)
    for (int idx = tid; idx < 128 * 25; idx += 512) {
        int rr = idx / 25, q = idx - rr * 25;
        ((float4*)U)[rr * 33 + q] =
            ((const float4*)distance)[(size_t)pbase * 25 + idx];
    }
    for (int idx = tid; idx < 100 * 32; idx += 512)
        ((float4*)Bs)[idx] = ((const float4*)W_df)[idx];
    __syncthreads();

    ull acc[16];
    {
        ull bl = pack2(bdf_s[c0],     bdf_s[c0 + 1]);
        ull bh = pack2(bdf_s[c0 + 2], bdf_s[c0 + 3]);
#pragma unroll
        for (int i = 0; i < 8; i++) { acc[2 * i] = bl; acc[2 * i + 1] = bh; }
    }
    {   // GEMM1: dh = dist @ W_df + b_df   (K = 100 = 25 blocks)
        const float* Arow = U + r0 * 132;
        const float* Bc   = Bs + c0;
#pragma unroll 2
        for (int k4 = 0; k4 < N_DIST; k4 += 4)
            gemm_block8x4<132>(Arow, Bc, k4, acc);
    }

    // m = dh * afh[j]  (gather; warp reads 512B contiguous per row)
#pragma unroll
    for (int i = 0; i < 8; i++) {
        const int j = j_s[r0 + i];
        ulonglong2 g = *(const ulonglong2*)(g_afh + (size_t)j * N_HID + c0);
        acc[2 * i]     = mul2(acc[2 * i],     g.x);
        acc[2 * i + 1] = mul2(acc[2 * i + 1], g.y);
    }
    __syncthreads();   // GEMM1 reads of U/Bs complete

    // store m row-major into U (stride 132); overwrite Bs with W_fc
#pragma unroll
    for (int i = 0; i < 8; i++) {
        ulonglong2 m; m.x = acc[2 * i]; m.y = acc[2 * i + 1];
        *(ulonglong2*)(U + (r0 + i) * 132 + c0) = m;
    }
    for (int idx = tid; idx < 128 * 32; idx += 512)
        ((float4*)Bs)[idx] = ((const float4*)W_fc)[idx];
    __syncthreads();

    // GEMM2: pre = m @ W_fc   (K = 128 = 32 blocks)
#pragma unroll
    for (int i = 0; i < 16; i++) acc[i] = 0ULL;
    {
        const float* Arow = U + r0 * 132;
        const float* Bc   = Bs + c0;
#pragma unroll 2
        for (int k4 = 0; k4 < N_HID; k4 += 4)
            gemm_block8x4<132>(Arow, Bc, k4, acc);
    }
    __syncthreads();   // all GEMM2 reads of U done

    // msg = tanh(pre) -> U
#pragma unroll
    for (int i = 0; i < 8; i++) {
        float l0, h0, l1, h1;
        unpack2(acc[2 * i],     l0, h0);
        unpack2(acc[2 * i + 1], l1, h1);
        float* mrow = U + (r0 + i) * 132 + c0;
        mrow[0] = fast_tanh(l0);
        mrow[1] = fast_tanh(h0);
        mrow[2] = fast_tanh(l1);
        mrow[3] = fast_tanh(h1);
    }
    __syncthreads();

    // Segmented reduction over sorted i: 512 threads = 128 cols x 4 quarters.
    {
        const int c  = tid & 127;
        const int h0 = (tid >> 7) << 5;   // 0, 32, 64, 96
        int   cur = i_s[h0];
        float sum = 0.0f;
        for (int rr = h0; rr < h0 + 32; rr++) {
            int ii = i_s[rr];
            if (ii != cur) {
                atomicAdd(out + (size_t)cur * N_EMB + c, sum);
                cur = ii; sum = 0.0f;
            }
            sum += U[rr * 132 + c];
        }
        atomicAdd(out + (size_t)cur * N_EMB + c, sum);
    }
}

// =====================================================================
extern "C" void kernel_launch(void* const* d_in, const int* in_sizes, int n_in,
                              void* d_out, int out_size)
{
    const float* atom_features = (const float*)d_in[0];
    const float* distance      = (const float*)d_in[1];
    const int*   dmi           = (const int*)d_in[3];
    const int*   dmj           = (const int*)d_in[4];
    const float* W_cf          = (const float*)d_in[5];
    const float* W_df          = (const float*)d_in[6];
    const float* W_fc          = (const float*)d_in[7];
    const float* b_cf          = (const float*)d_in[8];
    const float* b_df          = (const float*)d_in[9];
    float*       out           = (float*)d_out;

    const int smemA = (256 + 128*132 + 128*132 + 128*128) * 4;   // 201728 B
    const int smemP = (384 + 128*132 + 128*128) * 4;             // 134656 B

    cudaFuncSetAttribute(atoms_kernel, cudaFuncAttributeMaxDynamicSharedMemorySize, smemA);
    cudaFuncSetAttribute(pairs_kernel, cudaFuncAttributeMaxDynamicSharedMemorySize, smemP);

    atoms_kernel<<<(N_ATOMS + 127) / 128, 256, smemA>>>(
        atom_features, W_cf, W_fc, b_cf, b_df, out);
    pairs_kernel<<<N_PAIRS / 128, 512, smemP>>>(
        distance, dmi, dmj, W_df, W_fc, b_df, out);
}

// round 6
// speedup vs baseline: 1.9152x; 1.3256x over previous
#include <cuda_runtime.h>
#include <cuda_bf16.h>
#include <cstdint>

#define N_ATOMS 50000
#define N_PAIRS 800000
#define N_EMB   128
#define N_DIST  100
#define N_HID   128
#define BSTR    136          // padded bf16 row stride (272 B)

typedef unsigned long long ull;
typedef unsigned short ushort_t;

// ---------------- device scratch ----------------
__device__ float g_afh[(size_t)N_ATOMS * N_HID];                    // 25.6 MB
// n-major (transposed) padded bf16 images of W_df / W_fc, hi+lo splits
__device__ __align__(16) __nv_bfloat16 g_Bdf_hi[128 * BSTR];
__device__ __align__(16) __nv_bfloat16 g_Bdf_lo[128 * BSTR];
__device__ __align__(16) __nv_bfloat16 g_Bfc_hi[128 * BSTR];
__device__ __align__(16) __nv_bfloat16 g_Bfc_lo[128 * BSTR];

// ---------------- f32x2 helpers (atoms kernel) ----------------
static __device__ __forceinline__ void ffma2(ull &acc, ull a, ull b) {
    asm("fma.rn.f32x2 %0, %1, %2, %0;" : "+l"(acc) : "l"(a), "l"(b));
}
static __device__ __forceinline__ ull mul2(ull a, ull b) {
    ull r; asm("mul.rn.f32x2 %0, %1, %2;" : "=l"(r) : "l"(a), "l"(b)); return r;
}
static __device__ __forceinline__ ull pack2(float lo, float hi) {
    ull r; asm("mov.b64 %0, {%1, %2};" : "=l"(r) : "f"(lo), "f"(hi)); return r;
}
static __device__ __forceinline__ ull dup2(float v) {
    ull r; asm("mov.b64 %0, {%1, %1};" : "=l"(r) : "f"(v)); return r;
}
static __device__ __forceinline__ void unpack2(ull p, float &lo, float &hi) {
    asm("mov.b64 {%0, %1}, %2;" : "=f"(lo), "=f"(hi) : "l"(p));
}
static __device__ __forceinline__ float fast_tanh(float x) {
    float e = __expf(2.0f * x);
    return 1.0f - __fdividef(2.0f, e + 1.0f);
}
static __device__ __forceinline__ void split_bf(float x, ushort_t &h, ushort_t &l) {
    __nv_bfloat16 bh = __float2bfloat16(x);
    float r = x - __bfloat162float(bh);
    __nv_bfloat16 bl = __float2bfloat16(r);
    h = __bfloat16_as_ushort(bh);
    l = __bfloat16_as_ushort(bl);
}

// ---------------- mma / ldmatrix wrappers (sm_80+ features) ----------------
static __device__ __forceinline__ uint32_t smem_u32(const void* p) {
    uint32_t a;
    asm("{ .reg .u64 t; cvta.to.shared.u64 t, %1; cvt.u32.u64 %0, t; }"
        : "=r"(a) : "l"(p));
    return a;
}
static __device__ __forceinline__ void ldsm4(uint32_t* r, uint32_t addr) {
    asm volatile("ldmatrix.sync.aligned.m8n8.x4.shared.b16 {%0,%1,%2,%3}, [%4];"
                 : "=r"(r[0]), "=r"(r[1]), "=r"(r[2]), "=r"(r[3]) : "r"(addr));
}
static __device__ __forceinline__ void mma16816(float* d, const uint32_t* a,
                                                const uint32_t* b) {
    asm volatile(
        "mma.sync.aligned.m16n8k16.row.col.f32.bf16.bf16.f32 "
        "{%0,%1,%2,%3}, {%4,%5,%6,%7}, {%8,%9}, {%0,%1,%2,%3};"
        : "+f"(d[0]), "+f"(d[1]), "+f"(d[2]), "+f"(d[3])
        : "r"(a[0]), "r"(a[1]), "r"(a[2]), "r"(a[3]), "r"(b[0]), "r"(b[1]));
}

// ---------------- SMEM layout for pairs kernel (bytes) ----------------
#define SM_IS    0                        // 128 int
#define SM_JS    512                      // 128 int
#define SM_BDF   1024                     // 128 float
#define SM_AHI   2048                     // 128 x 136 bf16 = 34816 B
#define SM_ALO   (SM_AHI + 34816)
#define SM_BHI   (SM_ALO + 34816)
#define SM_BLO   (SM_BHI + 34816)
#define SM_TOTAL (SM_BLO + 34816)         // 141312 B
#define SM_MSG   SM_BHI                   // fp32 msg 128x129 (66048 B) reuses B

// =====================================================================
// Prep: n-major padded bf16 hi/lo images of W_df^T and W_fc^T
// =====================================================================
__global__ void prep_kernel(const float* __restrict__ W_df,
                            const float* __restrict__ W_fc)
{
    int idx = blockIdx.x * blockDim.x + threadIdx.x;   // 0..16383
    if (idx >= 16384) return;
    int n = idx >> 7;       // output column (B row in n-major image)
    int k = idx & 127;
    int o = n * BSTR + k;
    float vdf = (k < N_DIST) ? W_df[k * 128 + n] : 0.0f;
    float vfc = W_fc[k * 128 + n];
    ushort_t h, l;
    split_bf(vdf, h, l);
    g_Bdf_hi[o] = __ushort_as_bfloat16(h);
    g_Bdf_lo[o] = __ushort_as_bfloat16(l);
    split_bf(vfc, h, l);
    g_Bfc_hi[o] = __ushort_as_bfloat16(h);
    g_Bfc_lo[o] = __ushort_as_bfloat16(l);
}

// =====================================================================
// Atoms kernel: unchanged FFMA2 path (passing since R2)
// =====================================================================
template<int SA>
static __device__ __forceinline__ void gemm_step8(
    const float* __restrict__ Arow, const float* __restrict__ Bk,
    int k, ull acc[32])
{
    ull a2[8];
#pragma unroll
    for (int i = 0; i < 8; i++) a2[i] = dup2(Arow[i * SA + k]);
    ulonglong2 b01 = *(const ulonglong2*)(Bk);
    ulonglong2 b23 = *(const ulonglong2*)(Bk + 4);
#pragma unroll
    for (int i = 0; i < 8; i++) {
        ffma2(acc[i * 4 + 0], a2[i], b01.x);
        ffma2(acc[i * 4 + 1], a2[i], b01.y);
        ffma2(acc[i * 4 + 2], a2[i], b23.x);
        ffma2(acc[i * 4 + 3], a2[i], b23.y);
    }
}

__global__ void __launch_bounds__(256, 1) atoms_kernel(
    const float* __restrict__ atom_features,
    const float* __restrict__ W_cf,
    const float* __restrict__ W_fc,
    const float* __restrict__ b_cf,
    const float* __restrict__ b_df,
    float* __restrict__ out)
{
    extern __shared__ float smem[];
    float* bcf_s = smem;
    float* bdf_s = smem + 128;
    float* Af    = smem + 256;
    float* Ms    = Af + 128 * 132;
    float* Bs    = Ms + 128 * 132;

    const int tid = threadIdx.x;
    const int tx = tid & 15, ty = tid >> 4;
    const int c0 = tx * 8, r0 = ty * 8;
    const int base = blockIdx.x * 128;
    const int rows = min(128, N_ATOMS - base);

    if (tid < 128) { bcf_s[tid] = b_cf[tid]; bdf_s[tid] = b_df[tid]; }
    for (int idx = tid; idx < 128 * 32; idx += 256) {
        int rr = idx >> 5, q = idx & 31;
        float4 v = make_float4(0.f, 0.f, 0.f, 0.f);
        if (rr < rows) v = ((const float4*)atom_features)[(size_t)(base + rr) * 32 + q];
        ((float4*)Af)[rr * 33 + q] = v;
        ((float4*)Bs)[idx] = ((const float4*)W_cf)[idx];
    }
    __syncthreads();

    ull acc[32];
    {
        ull b[4];
#pragma unroll
        for (int q = 0; q < 4; q++) b[q] = pack2(bcf_s[c0 + 2*q], bcf_s[c0 + 2*q + 1]);
#pragma unroll
        for (int i = 0; i < 8; i++)
#pragma unroll
            for (int q = 0; q < 4; q++) acc[i * 4 + q] = b[q];
    }
    {
        const float* Arow = Af + r0 * 132;
        const float* Bc   = Bs + c0;
#pragma unroll 2
        for (int k = 0; k < 128; k++) gemm_step8<132>(Arow, Bc + k * 128, k, acc);
    }
#pragma unroll
    for (int i = 0; i < 8; i++) {
        if (base + r0 + i < N_ATOMS) {
            ull* arow = (ull*)(g_afh + (size_t)(base + r0 + i) * N_HID + c0);
#pragma unroll
            for (int q = 0; q < 4; q++) arow[q] = acc[i * 4 + q];
        }
    }
    __syncthreads();
#pragma unroll
    for (int i = 0; i < 8; i++) {
        ulonglong2 m01, m23;
        m01.x = mul2(acc[i*4+0], pack2(bdf_s[c0+0], bdf_s[c0+1]));
        m01.y = mul2(acc[i*4+1], pack2(bdf_s[c0+2], bdf_s[c0+3]));
        m23.x = mul2(acc[i*4+2], pack2(bdf_s[c0+4], bdf_s[c0+5]));
        m23.y = mul2(acc[i*4+3], pack2(bdf_s[c0+6], bdf_s[c0+7]));
        *(ulonglong2*)(Ms + (r0 + i) * 132 + c0)     = m01;
        *(ulonglong2*)(Ms + (r0 + i) * 132 + c0 + 4) = m23;
    }
    for (int idx = tid; idx < 128 * 32; idx += 256)
        ((float4*)Bs)[idx] = ((const float4*)W_fc)[idx];
    __syncthreads();

#pragma unroll
    for (int i = 0; i < 32; i++) acc[i] = 0ULL;
    {
        const float* Arow = Ms + r0 * 132;
        const float* Bc   = Bs + c0;
#pragma unroll 2
        for (int k = 0; k < 128; k++) gemm_step8<132>(Arow, Bc + k * 128, k, acc);
    }
#pragma unroll
    for (int i = 0; i < 8; i++) {
        if (base + r0 + i < N_ATOMS) {
            float* orow = out + (size_t)(base + r0 + i) * N_EMB + c0;
            const float* af = Af + (r0 + i) * 132 + c0;
#pragma unroll
            for (int q = 0; q < 4; q++) {
                float lo, hi; unpack2(acc[i * 4 + q], lo, hi);
                orow[2 * q]     = af[2 * q]     - fast_tanh(lo);
                orow[2 * q + 1] = af[2 * q + 1] - fast_tanh(hi);
            }
        }
    }
}

// =====================================================================
// Warp GEMM: D[128,128] over 8 warps (2 row-groups x 4 col-groups).
// Warp tile 64x32: 4 m16 tiles x 4 n8 tiles, 3-term bf16 split.
// =====================================================================
template<int KSTEPS>
static __device__ __forceinline__ void do_gemm(
    uint32_t aHi, uint32_t aLo, uint32_t bHi, uint32_t bLo,
    uint32_t aoff0, uint32_t boff0, float* d)
{
#pragma unroll 1
    for (int ks = 0; ks < KSTEPS; ks++) {
        uint32_t Ah[4][4], Al[4][4], Bh[4][2], Bl[4][2];
#pragma unroll
        for (int mt = 0; mt < 4; mt++) {
            uint32_t off = aoff0 + mt * (16 * BSTR * 2) + ks * 32;
            ldsm4(Ah[mt], aHi + off);
            ldsm4(Al[mt], aLo + off);
        }
#pragma unroll
        for (int np = 0; np < 2; np++) {
            uint32_t off = boff0 + np * (16 * BSTR * 2) + ks * 32;
            uint32_t th[4], tl[4];
            ldsm4(th, bHi + off);
            ldsm4(tl, bLo + off);
            Bh[2*np][0] = th[0]; Bh[2*np][1] = th[1];
            Bh[2*np+1][0] = th[2]; Bh[2*np+1][1] = th[3];
            Bl[2*np][0] = tl[0]; Bl[2*np][1] = tl[1];
            Bl[2*np+1][0] = tl[2]; Bl[2*np+1][1] = tl[3];
        }
#pragma unroll
        for (int mt = 0; mt < 4; mt++)
#pragma unroll
            for (int nt = 0; nt < 4; nt++) {
                float* dd = d + (mt * 4 + nt) * 4;
                mma16816(dd, Ah[mt], Bh[nt]);   // hi*hi
                mma16816(dd, Ah[mt], Bl[nt]);   // hi*lo
                mma16816(dd, Al[mt], Bh[nt]);   // lo*hi
            }
    }
}

// =====================================================================
// Pairs kernel (tensor path via mma.sync): 256 thr = 8 warps.
// =====================================================================
__global__ void __launch_bounds__(256, 1) pairs_kernel(
    const float* __restrict__ distance,
    const int*   __restrict__ dmi,
    const int*   __restrict__ dmj,
    const float* __restrict__ b_df,
    float* __restrict__ out)
{
    extern __shared__ char smc[];
    int*   i_s   = (int*)(smc + SM_IS);
    int*   j_s   = (int*)(smc + SM_JS);
    float* bdf_s = (float*)(smc + SM_BDF);
    const uint32_t sb  = smem_u32(smc);
    const uint32_t aHi = sb + SM_AHI, aLo = sb + SM_ALO;
    const uint32_t bHi = sb + SM_BHI, bLo = sb + SM_BLO;

    const int tid = threadIdx.x;
    const int wid = tid >> 5, lane = tid & 31;
    const int rg = wid >> 2, cg = wid & 3;
    const int pbase = blockIdx.x * 128;

    // ---- stage: distance splits (128 thr) + W_df images (128 thr) ----
    if (tid < 128) {
        const int row = tid;
        i_s[row]   = dmi[pbase + row];
        j_s[row]   = dmj[pbase + row];
        bdf_s[row] = b_df[row];
        const float4* dr = (const float4*)(distance + (size_t)(pbase + row) * N_DIST);
        char* ah = smc + SM_AHI + row * (BSTR * 2);
        char* al = smc + SM_ALO + row * (BSTR * 2);
#pragma unroll
        for (int q = 0; q < 25; q++) {
            float4 v = dr[q];
            ushort_t h0,l0,h1,l1,h2,l2,h3,l3;
            split_bf(v.x, h0, l0); split_bf(v.y, h1, l1);
            split_bf(v.z, h2, l2); split_bf(v.w, h3, l3);
            *(unsigned*)(ah + 8 * q)     = (unsigned)h0 | ((unsigned)h1 << 16);
            *(unsigned*)(ah + 8 * q + 4) = (unsigned)h2 | ((unsigned)h3 << 16);
            *(unsigned*)(al + 8 * q)     = (unsigned)l0 | ((unsigned)l1 << 16);
            *(unsigned*)(al + 8 * q + 4) = (unsigned)l2 | ((unsigned)l3 << 16);
        }
#pragma unroll
        for (int c = 100; c < 112; c += 2) {   // zero pad (GEMM1 runs 7 ksteps)
            *(unsigned*)(ah + c * 2) = 0u;
            *(unsigned*)(al + c * 2) = 0u;
        }
    } else {
        const int t = tid - 128;
        for (int q = t; q < 2176; q += 128) {
            ((uint4*)(smc + SM_BHI))[q] = ((const uint4*)g_Bdf_hi)[q];
            ((uint4*)(smc + SM_BLO))[q] = ((const uint4*)g_Bdf_lo)[q];
        }
    }
    __syncthreads();

    // lane-level ldmatrix address components
    const int arow  = (lane & 7) + 8 * ((lane >> 3) & 1);
    const int acolb = 16 * (lane >> 4);
    const int brow  = (lane & 7) + 8 * (lane >> 4);
    const int bcolb = 16 * ((lane >> 3) & 1);
    const uint32_t aoff0 = (uint32_t)((rg * 64 + arow) * (BSTR * 2) + acolb);
    const uint32_t boff0 = (uint32_t)((cg * 32 + brow) * (BSTR * 2) + bcolb);

    float d[64];
#pragma unroll
    for (int i = 0; i < 64; i++) d[i] = 0.0f;

    // ---- GEMM1: dh = dist @ W_df (K=112 incl. zero pad) ----
    do_gemm<7>(aHi, aLo, bHi, bLo, aoff0, boff0, d);
    __syncthreads();   // all ldmatrix reads done before A region overwrite

    // ---- Epilogue 1: m = (dh + b_df) * afh[j]; split back into A ----
    {
        const int g = lane >> 2, tg = lane & 3;
#pragma unroll
        for (int mt = 0; mt < 4; mt++)
#pragma unroll
            for (int f2 = 0; f2 < 2; f2++) {
                const int row = rg * 64 + mt * 16 + 8 * f2 + g;
                const int j = j_s[row];
                const float* ar = g_afh + (size_t)j * N_HID;
                char* ah = smc + SM_AHI + row * (BSTR * 2);
                char* al = smc + SM_ALO + row * (BSTR * 2);
#pragma unroll
                for (int nt = 0; nt < 4; nt++) {
                    const int c = cg * 32 + nt * 8 + 2 * tg;
                    float2 af = *(const float2*)(ar + c);
                    float v0 = (d[(mt*4+nt)*4 + 2*f2]     + bdf_s[c])     * af.x;
                    float v1 = (d[(mt*4+nt)*4 + 2*f2 + 1] + bdf_s[c + 1]) * af.y;
                    ushort_t h0, l0, h1, l1;
                    split_bf(v0, h0, l0); split_bf(v1, h1, l1);
                    *(unsigned*)(ah + c * 2) = (unsigned)h0 | ((unsigned)h1 << 16);
                    *(unsigned*)(al + c * 2) = (unsigned)l0 | ((unsigned)l1 << 16);
                }
            }
    }
    // swap in W_fc images
    for (int q = tid; q < 2176; q += 256) {
        ((uint4*)(smc + SM_BHI))[q] = ((const uint4*)g_Bfc_hi)[q];
        ((uint4*)(smc + SM_BLO))[q] = ((const uint4*)g_Bfc_lo)[q];
    }
    __syncthreads();

    // ---- GEMM2: pre = m @ W_fc (K=128) ----
#pragma unroll
    for (int i = 0; i < 64; i++) d[i] = 0.0f;
    do_gemm<8>(aHi, aLo, bHi, bLo, aoff0, boff0, d);
    __syncthreads();   // B-region reads done before msg overwrite

    // ---- Epilogue 2: msg = tanh(pre) ----
    {
        float* msg = (float*)(smc + SM_MSG);
        const int g = lane >> 2, tg = lane & 3;
#pragma unroll
        for (int mt = 0; mt < 4; mt++)
#pragma unroll
            for (int f2 = 0; f2 < 2; f2++) {
                const int row = rg * 64 + mt * 16 + 8 * f2 + g;
#pragma unroll
                for (int nt = 0; nt < 4; nt++) {
                    const int c = cg * 32 + nt * 8 + 2 * tg;
                    msg[row * 129 + c]     = fast_tanh(d[(mt*4+nt)*4 + 2*f2]);
                    msg[row * 129 + c + 1] = fast_tanh(d[(mt*4+nt)*4 + 2*f2 + 1]);
                }
            }
    }
    __syncthreads();

    // ---- Segment sum over sorted i: 256 thr = 128 cols x 2 halves ----
    {
        const float* msg = (const float*)(smc + SM_MSG);
        const int c  = tid & 127;
        const int h0 = (tid >> 7) * 64;
        int   cur = i_s[h0];
        float sum = 0.0f;
        for (int rr = h0; rr < h0 + 64; rr++) {
            int ii = i_s[rr];
            if (ii != cur) {
                atomicAdd(out + (size_t)cur * N_EMB + c, sum);
                cur = ii; sum = 0.0f;
            }
            sum += msg[rr * 129 + c];
        }
        atomicAdd(out + (size_t)cur * N_EMB + c, sum);
    }
}

// =====================================================================
extern "C" void kernel_launch(void* const* d_in, const int* in_sizes, int n_in,
                              void* d_out, int out_size)
{
    const float* atom_features = (const float*)d_in[0];
    const float* distance      = (const float*)d_in[1];
    const int*   dmi           = (const int*)d_in[3];
    const int*   dmj           = (const int*)d_in[4];
    const float* W_cf          = (const float*)d_in[5];
    const float* W_df          = (const float*)d_in[6];
    const float* W_fc          = (const float*)d_in[7];
    const float* b_cf          = (const float*)d_in[8];
    const float* b_df          = (const float*)d_in[9];
    float*       out           = (float*)d_out;

    const int smemA = (256 + 128*132 + 128*132 + 128*128) * 4;   // 201728 B

    cudaFuncSetAttribute(atoms_kernel, cudaFuncAttributeMaxDynamicSharedMemorySize, smemA);
    cudaFuncSetAttribute(pairs_kernel, cudaFuncAttributeMaxDynamicSharedMemorySize, SM_TOTAL);

    prep_kernel<<<64, 256>>>(W_df, W_fc);
    atoms_kernel<<<(N_ATOMS + 127) / 128, 256, smemA>>>(
        atom_features, W_cf, W_fc, b_cf, b_df, out);
    pairs_kernel<<<N_PAIRS / 128, 256, SM_TOTAL>>>(
        distance, dmi, dmj, b_df, out);
}